// round 16
// baseline (speedup 1.0000x reference)
#include <cuda_runtime.h>
#include <cuda_fp16.h>
#include <cstdint>

#define BB 16
#define TTOK 256
#define DD 1024
#define QKVW 3072
#define HH 16
#define NBLK 6
#define GDIM 300
#define GPAD 320
#define MLPH 2048
#define FFH 4096
#define DH 64
#define NTOK (BB*TTOK)   // 4096

// ---------------- scratch (device globals; no allocation allowed) ----------------
__device__ float g_xe [NTOK*GDIM];
__device__ float g_x  [NTOK*DD];
__device__ float g_o  [NTOK*DD];
__device__ float g_bqkv[NBLK*QKVW];

// fp16 activations (hi planes; lo only where consumed)
__device__ __align__(16) uint16_t g_xeh[NTOK*GPAD];
__device__ __align__(16) uint16_t g_xh [NTOK*DD];
__device__ __align__(16) uint16_t g_h1h[NTOK*MLPH];
__device__ __align__(16) uint16_t g_ffh[(size_t)NTOK*FFH];
__device__ __align__(16) uint16_t g_qkvh[(size_t)NTOK*QKVW], g_qkvl[(size_t)NTOK*QKVW];
__device__ __align__(16) uint16_t g_ph[(size_t)BB*HH*TTOK*TTOK], g_pl[(size_t)BB*HH*TTOK*TTOK];
// V transposed per (b,h): [z][dh=64][keys/2=128 words] (hi only)
__device__ uint32_t g_vth[(size_t)BB*HH*DH*(TTOK/2)];

// packed fp16 weights (HI plane only), N-MAJOR: [N][K/2] fp16x2
#define OFF_MLP1 0ull
#define OFF_MLP2 327680ull
#define OFF_QKV  1376256ull
#define QKV_BLK  1572864ull
#define QKV_MAT  524288ull
#define OFF_FF1  10813440ull
#define FF1_BLK  2097152ull
#define OFF_FF2  23396352ull
#define FF2_BLK  2097152ull
#define W_TOTAL  35979264ull
__device__ uint32_t g_wh[W_TOTAL];

// ---------------- fp16 split helpers ----------------
__device__ __forceinline__ uint32_t pack_hi(float a, float b) {
    __half2 t = __floats2half2_rn(a, b);
    return *reinterpret_cast<uint32_t*>(&t);
}
__device__ __forceinline__ uint32_t pack_lo(float a, float b) {
    float ra = a - __half2float(__float2half_rn(a));
    float rb = b - __half2float(__float2half_rn(b));
    __half2 t = __floats2half2_rn(ra, rb);
    return *reinterpret_cast<uint32_t*>(&t);
}
__device__ __forceinline__ uint16_t hi16(float v) {
    __half h = __float2half_rn(v);
    return *reinterpret_cast<uint16_t*>(&h);
}

// ---------------- transpose-pack: W[K][N] fp32 -> n-major [N][Kpad/2] fp16x2 (hi only) ----------------
__global__ void pack_wt(const float* __restrict__ W, uint32_t* __restrict__ oh,
                        int K, int N, int Kpad, size_t matStride, size_t outBlk) {
    __shared__ float st[64][33];
    W  += (size_t)blockIdx.z * matStride;
    oh += (size_t)blockIdx.z * outBlk;
    const int n0 = blockIdx.x * 32, k0 = blockIdx.y * 64;
    const int t = threadIdx.x;
    const int kk = t >> 5, n = t & 31;
#pragma unroll
    for (int i = 0; i < 8; i++) {
        int krow = k0 + kk + i * 8;
        st[kk + i * 8][n] = (krow < K) ? W[(size_t)krow * N + n0 + n] : 0.f;
    }
    __syncthreads();
    const int nn = t >> 3, c4 = (t & 7) * 4;
    uint32_t hv[4];
#pragma unroll
    for (int j = 0; j < 4; j++) {
        int k2 = c4 + j;
        hv[j] = pack_hi(st[2 * k2][nn], st[2 * k2 + 1][nn]);
    }
    size_t o = (size_t)(n0 + nn) * (Kpad >> 1) + (k0 >> 1) + c4;
    *(uint4*)(oh + o) = make_uint4(hv[0], hv[1], hv[2], hv[3]);
}

__global__ void pack_bias(const float* __restrict__ bq, const float* __restrict__ bk,
                          const float* __restrict__ bv) {
    int idx = blockIdx.x * 256 + threadIdx.x;
    if (idx >= NBLK * QKVW) return;
    int blk = idx / QKVW, n = idx - blk * QKVW;
    float v;
    if (n < DD)           v = bq[blk * DD + n];
    else if (n < 2 * DD)  v = bk[blk * DD + n - DD];
    else                  v = bv[blk * DD + n - 2 * DD];
    g_bqkv[idx] = v;
}

// ---------------- embedding gather + hi-convert ----------------
__global__ void embed_gather(const int* __restrict__ ids, const float* __restrict__ emb) {
    int idx = blockIdx.x * blockDim.x + threadIdx.x;
    if (idx >= NTOK * GDIM) return;
    int bt = idx / GDIM;
    int c  = idx - bt * GDIM;
    g_xe[idx] = emb[(long long)ids[bt] * GDIM + c];
}
__global__ void conv_xe() {
    int idx = blockIdx.x * 256 + threadIdx.x;
    if (idx >= NTOK * GPAD) return;
    int m = idx / GPAD, k = idx - m * GPAD;
    float v = (k < GDIM) ? g_xe[m * GDIM + k] : 0.f;
    g_xeh[idx] = hi16(v);
}

__global__ void add_pos(const float* __restrict__ pos) {
    int idx = blockIdx.x * blockDim.x + threadIdx.x;
    if (idx >= NTOK * DD) return;
    float v = g_x[idx] + pos[idx % (TTOK * DD)];
    g_x[idx] = v;
    g_xh[idx] = hi16(v);
}

// ---------------- V transpose (hi plane only) ----------------
__global__ void __launch_bounds__(256) v_trans() {
    __shared__ uint16_t sh[64][65];
    const int kt = blockIdx.x, z = blockIdx.y;
    const int zb = z >> 4, zh = z & 15;
    const int t = threadIdx.x;
    const size_t base = (size_t)zb * TTOK * QKVW + 2 * DD + (size_t)zh * DH;
#pragma unroll
    for (int i = 0; i < 16; i++) {
        int e = t + i * 256;
        int r = e >> 6, c = e & 63;
        sh[r][c] = g_qkvh[base + (size_t)(kt * 64 + r) * QKVW + c];
    }
    __syncthreads();
    const int d = t >> 2, w0 = (t & 3) * 8;
    size_t ob = (size_t)z * (DH * TTOK / 2) + (size_t)d * (TTOK / 2) + kt * 32;
#pragma unroll
    for (int j = 0; j < 8; j++) {
        int w = w0 + j;
        g_vth[ob + w] = (uint32_t)sh[2 * w][d] | ((uint32_t)sh[2 * w + 1][d] << 16);
    }
}

// ---------------- async / mma helpers ----------------
__device__ __forceinline__ uint32_t smem_u32(const void* p) {
    uint32_t a;
    asm("{ .reg .u64 t; cvta.to.shared.u64 t, %1; cvt.u32.u64 %0, t; }" : "=r"(a) : "l"(p));
    return a;
}
__device__ __forceinline__ void cp16(uint32_t saddr, const void* g) {
    asm volatile("cp.async.cg.shared.global [%0], [%1], 16;" :: "r"(saddr), "l"(g));
}
__device__ __forceinline__ void cp_commit() {
    asm volatile("cp.async.commit_group;" ::: "memory");
}
template<int N>
__device__ __forceinline__ void cp_wait() {
    asm volatile("cp.async.wait_group %0;" :: "n"(N) : "memory");
}

#define MMA_F16(d, a, b)                                                         \
    asm volatile("mma.sync.aligned.m16n8k16.row.col.f32.f16.f16.f32 "            \
                 "{%0,%1,%2,%3},{%4,%5,%6,%7},{%8,%9},{%0,%1,%2,%3};"            \
                 : "+f"(d[0]), "+f"(d[1]), "+f"(d[2]), "+f"(d[3])                 \
                 : "r"(a[0]), "r"(a[1]), "r"(a[2]), "r"(a[3]), "r"(b[0]), "r"(b[1]))

#define LDSM4(r0, r1, r2, r3, addr)                                              \
    asm volatile("ldmatrix.sync.aligned.m8n8.x4.shared.b16 {%0,%1,%2,%3}, [%4];" \
                 : "=r"(r0), "=r"(r1), "=r"(r2), "=r"(r3) : "r"(addr))

// ---------------- generalized fp16 HGEMM (weight GEMMs + AV) ----------------
// TERMS=1: Ah@Wh, 3-stage, ONE barrier/ktile. TERMS=2: (Ah+Al)@Wh, 2-stage.
// MODE 0: fp32 +bias. MODE 1: split fp16 hi+lo +bias. MODE 2: fp32 no bias. MODE 3: fp16 hi +bias.
template<int MT, int NT, int MODE, bool RELU, int TERMS>
__global__ void __launch_bounds__(128, 2)
hgemm(const uint16_t* __restrict__ Ah, const uint16_t* __restrict__ Al,
      const uint32_t* __restrict__ Wh,
      const float* __restrict__ bias,
      float* __restrict__ C, uint16_t* __restrict__ Ch, uint16_t* __restrict__ Cl,
      int M, int N, int K, int sA, int sWw, int sC,
      size_t ozAb, size_t ozAh, size_t ozWb, size_t ozWh, size_t ozCb, size_t ozCh) {
    constexpr int APL  = MT * 80;
    constexpr int WPL  = NT * 80;
    constexpr int APLN = (TERMS >= 2) ? 2 : 1;
    constexpr int ALO  = APL;
    constexpr int WOFF = APLN * APL;
    constexpr int STG  = APLN * APL + WPL;
    constexpr int NSTG = (TERMS >= 2) ? 2 : 3;

    extern __shared__ char smc[];
    const uint32_t smb = smem_u32(smc);
    const int tid  = threadIdx.x;
    const int lane = tid & 31, warp = tid >> 5;
    const int wm   = (MT == 256) ? warp * 64 : (warp >> 1) * 64;
    const int wn   = (MT == 256) ? 0         : (warp & 1) * 64;
    const int group = lane >> 2, quad = lane & 3;
    const int row0 = blockIdx.y * MT;
    const int col0 = blockIdx.x * NT;

    const int z = blockIdx.z, zb = z >> 4, zh = z & 15;
    Ah += zb * ozAb + zh * ozAh;
    if (TERMS >= 2) Al += zb * ozAb + zh * ozAh;
    Wh += zb * ozWb + zh * ozWh;
    const size_t czoff = zb * ozCb + zh * ozCh;

    const int sub = lane >> 3, rr = lane & 7;
    const uint32_t aOff = ((wm + (sub & 1) * 8 + rr) * 40 + (sub >> 1) * 8) * 2;
    const uint32_t wOff = WOFF + ((wn + (sub >> 1) * 8 + rr) * 20 + (sub & 1) * 4) * 4;

    float acc[4][8][4];
#pragma unroll
    for (int i = 0; i < 4; i++)
#pragma unroll
        for (int j = 0; j < 8; j++)
#pragma unroll
            for (int e = 0; e < 4; e++) acc[i][j][e] = 0.f;

    const int iters = K >> 5;

    auto fill = [&](int stage, int k0) {
        uint32_t sb = smb + stage * STG;
#pragma unroll
        for (int i = 0; i < MT / 32; i++) {
            int c = tid + i * 128;
            int row = c >> 2, kc = c & 3;
            size_t g = (size_t)(row0 + row) * sA + k0 + kc * 8;
            uint32_t so = sb + row * 80 + kc * 16;
            cp16(so, Ah + g);
            if (TERMS >= 2) cp16(so + ALO, Al + g);
        }
        const int k2b = k0 >> 1;
#pragma unroll
        for (int i = 0; i < NT / 32; i++) {
            int c = tid + i * 128;
            int row = c >> 2, ch = c & 3;
            size_t g = (size_t)(col0 + row) * sWw + k2b + ch * 4;
            uint32_t so = sb + WOFF + row * 80 + ch * 16;
            cp16(so, Wh + g);
        }
    };

    auto compute = [&](int stage) {
        const uint32_t aBase = smb + stage * STG + aOff;
        const uint32_t wBase = smb + stage * STG + wOff;
#pragma unroll
        for (int ks = 0; ks < 2; ks++) {
            uint32_t wh_[4][4];
#pragma unroll
            for (int p = 0; p < 4; p++) {
                LDSM4(wh_[p][0], wh_[p][1], wh_[p][2], wh_[p][3], wBase + p * 1280 + ks * 32);
            }
#pragma unroll
            for (int mt = 0; mt < 4; mt++) {
                uint32_t ah[4], al[4];
                LDSM4(ah[0], ah[1], ah[2], ah[3], aBase + mt * 1280 + ks * 32);
                if (TERMS >= 2)
                    LDSM4(al[0], al[1], al[2], al[3], aBase + ALO + mt * 1280 + ks * 32);
#pragma unroll
                for (int nt = 0; nt < 8; nt++) MMA_F16(acc[mt][nt], ah, (&wh_[nt >> 1][(nt & 1) * 2]));
                if (TERMS >= 2) {
#pragma unroll
                    for (int nt = 0; nt < 8; nt++) MMA_F16(acc[mt][nt], al, (&wh_[nt >> 1][(nt & 1) * 2]));
                }
            }
        }
    };

    if (TERMS == 1) {
        fill(0, 0); cp_commit();
        if (iters > 1) { fill(1, 32); cp_commit(); }
        for (int it = 0; it < iters; ++it) {
            if (it + 1 < iters) cp_wait<1>(); else cp_wait<0>();
            __syncthreads();
            if (it + 2 < iters) { fill((it + 2) % NSTG, (it + 2) * 32); cp_commit(); }
            compute(it % NSTG);
        }
        __syncthreads();
    } else {
        fill(0, 0); cp_commit();
        for (int it = 0; it < iters; ++it) {
            if (it + 1 < iters) { fill((it + 1) & 1, (it + 1) * 32); cp_commit(); cp_wait<1>(); }
            else cp_wait<0>();
            __syncthreads();
            compute(it & 1);
            __syncthreads();
        }
    }

    // ---- epilogue ----
#pragma unroll
    for (int mt = 0; mt < 4; mt++) {
        int r = row0 + wm + mt * 16 + group;
#pragma unroll
        for (int nt = 0; nt < 8; nt++) {
            int c  = col0 + wn + nt * 8 + quad * 2;
            float b0 = 0.f, b1 = 0.f;
            if (MODE != 2) { b0 = bias[c]; b1 = bias[c + 1]; }
            float v0 = acc[mt][nt][0] + b0;
            float v1 = acc[mt][nt][1] + b1;
            float v2 = acc[mt][nt][2] + b0;
            float v3 = acc[mt][nt][3] + b1;
            if (RELU) {
                v0 = fmaxf(v0, 0.f); v1 = fmaxf(v1, 0.f);
                v2 = fmaxf(v2, 0.f); v3 = fmaxf(v3, 0.f);
            }
            if (MODE == 1 || MODE == 3) {
                uint32_t* ChW = (uint32_t*)Ch;
                size_t i0 = (czoff + (size_t)r * sC + c) >> 1;
                size_t i1 = (czoff + (size_t)(r + 8) * sC + c) >> 1;
                ChW[i0] = pack_hi(v0, v1);
                ChW[i1] = pack_hi(v2, v3);
                if (MODE == 1) {
                    uint32_t* ClW = (uint32_t*)Cl;
                    ClW[i0] = pack_lo(v0, v1);
                    ClW[i1] = pack_lo(v2, v3);
                }
            } else {
                *(float2*)&C[czoff + (size_t)r * sC + c]       = make_float2(v0, v1);
                *(float2*)&C[czoff + (size_t)(r + 8) * sC + c] = make_float2(v2, v3);
            }
        }
    }
}

// ---------------- fused scores + masked softmax ----------------
// Tile 128(q) x 256(all keys) per CTA; 8 warps of 64x64; 2-term (Qh+Ql)@Kh.
// Epilogue: scale, mask, softmax over the full row (in-CTA), write split-fp16 probs.
#define ATT_STG 40960     // Ah 10240 | Al 10240 | W 20480
#define SM_ATT  (2*ATT_STG)
__global__ void __launch_bounds__(256, 1)
attn_sm(const uint16_t* __restrict__ qh, const uint16_t* __restrict__ ql,
        const int* __restrict__ smask, const int* __restrict__ graph) {
    constexpr int APL  = 128 * 80;
    constexpr int WOFF = 2 * APL;

    extern __shared__ char smc[];
    const uint32_t smb = smem_u32(smc);
    const int tid  = threadIdx.x;
    const int lane = tid & 31, warp = tid >> 5;
    const int wm   = (warp >> 2) * 64;       // 0/64
    const int wn   = (warp & 3) * 64;        // 0/64/128/192
    const int wnIdx = warp & 3;
    const int group = lane >> 2, quad = lane & 3;
    const int q0 = blockIdx.x * 128;
    const int z = blockIdx.y, zb = z >> 4, zh = z & 15;

    const uint16_t* Ah = qh + (size_t)zb * TTOK * QKVW + zh * DH;
    const uint16_t* Al = ql + (size_t)zb * TTOK * QKVW + zh * DH;
    const uint32_t* Wr = (const uint32_t*)qh + (size_t)zb * TTOK * (QKVW / 2) + DD / 2 + zh * (DH / 2);

    const int sub = lane >> 3, rr = lane & 7;
    const uint32_t aOff = ((wm + (sub & 1) * 8 + rr) * 40 + (sub >> 1) * 8) * 2;
    const uint32_t wOff = WOFF + ((wn + (sub >> 1) * 8 + rr) * 20 + (sub & 1) * 4) * 4;

    float acc[4][8][4];
#pragma unroll
    for (int i = 0; i < 4; i++)
#pragma unroll
        for (int j = 0; j < 8; j++)
#pragma unroll
            for (int e = 0; e < 4; e++) acc[i][j][e] = 0.f;

    auto fill = [&](int stage, int k0) {
        uint32_t sb = smb + stage * ATT_STG;
#pragma unroll
        for (int i = 0; i < 2; i++) {            // Q: 128 rows x 4 chunks
            int c = tid + i * 256;
            int row = c >> 2, kc = c & 3;
            size_t g = (size_t)(q0 + row) * QKVW + k0 + kc * 8;
            uint32_t so = sb + row * 80 + kc * 16;
            cp16(so, Ah + g);
            cp16(so + APL, Al + g);
        }
#pragma unroll
        for (int i = 0; i < 4; i++) {            // K: 256 rows x 4 chunks (words)
            int c = tid + i * 256;
            int row = c >> 2, ch = c & 3;
            size_t g = (size_t)row * (QKVW / 2) + (k0 >> 1) + ch * 4;
            cp16(sb + WOFF + row * 80 + ch * 16, Wr + g);
        }
    };

    auto compute = [&](int stage) {
        const uint32_t aBase = smb + stage * ATT_STG + aOff;
        const uint32_t wBase = smb + stage * ATT_STG + wOff;
#pragma unroll
        for (int ks = 0; ks < 2; ks++) {
            uint32_t wh_[4][4];
#pragma unroll
            for (int p = 0; p < 4; p++)
                LDSM4(wh_[p][0], wh_[p][1], wh_[p][2], wh_[p][3], wBase + p * 1280 + ks * 32);
#pragma unroll
            for (int mt = 0; mt < 4; mt++) {
                uint32_t ah[4], al[4];
                LDSM4(ah[0], ah[1], ah[2], ah[3], aBase + mt * 1280 + ks * 32);
                LDSM4(al[0], al[1], al[2], al[3], aBase + APL + mt * 1280 + ks * 32);
#pragma unroll
                for (int nt = 0; nt < 8; nt++) MMA_F16(acc[mt][nt], ah, (&wh_[nt >> 1][(nt & 1) * 2]));
#pragma unroll
                for (int nt = 0; nt < 8; nt++) MMA_F16(acc[mt][nt], al, (&wh_[nt >> 1][(nt & 1) * 2]));
            }
        }
    };

    // K = 64 -> 2 ktiles, 2-stage
    fill(0, 0); cp_commit();
    fill(1, 32); cp_commit();
    cp_wait<1>(); __syncthreads();
    compute(0);
    cp_wait<0>(); __syncthreads();
    compute(1);
    __syncthreads();

    // ---- fused masked softmax over full rows ----
    float* red = (float*)smc;                    // reuse stage smem: [4][128]
    const int* km = smask + zb * TTOK;
    const int* gb = graph + ((size_t)zb * TTOK + q0) * TTOK;
    const float NEGF = -4294967295.0f;

    // scale + mask, per-thread row maxes
    float rmax[4][2];
#pragma unroll
    for (int mt = 0; mt < 4; mt++) { rmax[mt][0] = -3.4e38f; rmax[mt][1] = -3.4e38f; }
#pragma unroll
    for (int mt = 0; mt < 4; mt++) {
        const int r0 = wm + mt * 16 + group;
#pragma unroll
        for (int nt = 0; nt < 8; nt++) {
            const int c = wn + nt * 8 + quad * 2;
            const int k0v = km[c], k1v = km[c + 1];
            int2 ga = *(const int2*)(gb + (size_t)r0 * TTOK + c);
            int2 gc = *(const int2*)(gb + (size_t)(r0 + 8) * TTOK + c);
            float s0 = acc[mt][nt][0] * 0.125f;
            float s1 = acc[mt][nt][1] * 0.125f;
            float s2 = acc[mt][nt][2] * 0.125f;
            float s3 = acc[mt][nt][3] * 0.125f;
            if (!(k0v > 0 && ga.x > 0)) s0 = NEGF;
            if (!(k1v > 0 && ga.y > 0)) s1 = NEGF;
            if (!(k0v > 0 && gc.x > 0)) s2 = NEGF;
            if (!(k1v > 0 && gc.y > 0)) s3 = NEGF;
            acc[mt][nt][0] = s0; acc[mt][nt][1] = s1;
            acc[mt][nt][2] = s2; acc[mt][nt][3] = s3;
            rmax[mt][0] = fmaxf(rmax[mt][0], fmaxf(s0, s1));
            rmax[mt][1] = fmaxf(rmax[mt][1], fmaxf(s2, s3));
        }
    }
    // quad reduce + cross-warp max
#pragma unroll
    for (int mt = 0; mt < 4; mt++)
#pragma unroll
        for (int h = 0; h < 2; h++) {
            float m = rmax[mt][h];
            m = fmaxf(m, __shfl_xor_sync(0xffffffffu, m, 1));
            m = fmaxf(m, __shfl_xor_sync(0xffffffffu, m, 2));
            rmax[mt][h] = m;
        }
    if (quad == 0) {
#pragma unroll
        for (int mt = 0; mt < 4; mt++)
#pragma unroll
            for (int h = 0; h < 2; h++)
                red[wnIdx * 128 + wm + mt * 16 + group + h * 8] = rmax[mt][h];
    }
    __syncthreads();
    float gmax[4][2];
#pragma unroll
    for (int mt = 0; mt < 4; mt++)
#pragma unroll
        for (int h = 0; h < 2; h++) {
            int r = wm + mt * 16 + group + h * 8;
            gmax[mt][h] = fmaxf(fmaxf(red[r], red[128 + r]),
                                fmaxf(red[256 + r], red[384 + r]));
        }
    __syncthreads();

    // exp + row sums
    float rsum[4][2];
#pragma unroll
    for (int mt = 0; mt < 4; mt++) { rsum[mt][0] = 0.f; rsum[mt][1] = 0.f; }
#pragma unroll
    for (int mt = 0; mt < 4; mt++)
#pragma unroll
        for (int nt = 0; nt < 8; nt++) {
            float e0 = expf(acc[mt][nt][0] - gmax[mt][0]);
            float e1 = expf(acc[mt][nt][1] - gmax[mt][0]);
            float e2 = expf(acc[mt][nt][2] - gmax[mt][1]);
            float e3 = expf(acc[mt][nt][3] - gmax[mt][1]);
            acc[mt][nt][0] = e0; acc[mt][nt][1] = e1;
            acc[mt][nt][2] = e2; acc[mt][nt][3] = e3;
            rsum[mt][0] += e0 + e1;
            rsum[mt][1] += e2 + e3;
        }
#pragma unroll
    for (int mt = 0; mt < 4; mt++)
#pragma unroll
        for (int h = 0; h < 2; h++) {
            float s = rsum[mt][h];
            s += __shfl_xor_sync(0xffffffffu, s, 1);
            s += __shfl_xor_sync(0xffffffffu, s, 2);
            rsum[mt][h] = s;
        }
    if (quad == 0) {
#pragma unroll
        for (int mt = 0; mt < 4; mt++)
#pragma unroll
            for (int h = 0; h < 2; h++)
                red[wnIdx * 128 + wm + mt * 16 + group + h * 8] = rsum[mt][h];
    }
    __syncthreads();
    float inv[4][2];
#pragma unroll
    for (int mt = 0; mt < 4; mt++)
#pragma unroll
        for (int h = 0; h < 2; h++) {
            int r = wm + mt * 16 + group + h * 8;
            float tot = red[r] + red[128 + r] + red[256 + r] + red[384 + r];
            inv[mt][h] = (float)km[0 - 0 + (q0 + r)] / tot;   // qscale = smask[b, q]
        }

    // write split-fp16 probs
    uint32_t* PhW = (uint32_t*)g_ph;
    uint32_t* PlW = (uint32_t*)g_pl;
    const size_t zoff = (size_t)z * TTOK * TTOK;
#pragma unroll
    for (int mt = 0; mt < 4; mt++) {
        const int r0 = q0 + wm + mt * 16 + group;
#pragma unroll
        for (int nt = 0; nt < 8; nt++) {
            const int c = wn + nt * 8 + quad * 2;
            float p0 = acc[mt][nt][0] * inv[mt][0];
            float p1 = acc[mt][nt][1] * inv[mt][0];
            float p2 = acc[mt][nt][2] * inv[mt][1];
            float p3 = acc[mt][nt][3] * inv[mt][1];
            size_t i0 = (zoff + (size_t)r0 * TTOK + c) >> 1;
            size_t i1 = (zoff + (size_t)(r0 + 8) * TTOK + c) >> 1;
            PhW[i0] = pack_hi(p0, p1); PlW[i0] = pack_lo(p0, p1);
            PhW[i1] = pack_hi(p2, p3); PlW[i1] = pack_lo(p2, p3);
        }
    }
}

// ---------------- residual + layernorm (+ hi write) ----------------
__global__ void __launch_bounds__(256) ln_res(const float* __restrict__ addsrc,
                                              const float* __restrict__ gam,
                                              const float* __restrict__ bet) {
    const int row = blockIdx.x;
    const int tid = threadIdx.x;
    const int warp = tid >> 5, lane = tid & 31;
    float* xr = g_x + (size_t)row * DD;
    const float* ar = addsrc + (size_t)row * DD;
    __shared__ float red[8];

    float vals[4];
    float s = 0.f;
#pragma unroll
    for (int j = 0; j < 4; j++) {
        int c = tid + j * 256;
        vals[j] = xr[c] + ar[c];
        s += vals[j];
    }
#pragma unroll
    for (int off = 16; off >= 1; off >>= 1) s += __shfl_xor_sync(0xffffffffu, s, off);
    if (lane == 0) red[warp] = s;
    __syncthreads();
    float tot = 0.f;
#pragma unroll
    for (int w = 0; w < 8; w++) tot += red[w];
    const float mean = tot * (1.f / 1024.f);
    __syncthreads();

    float vs = 0.f;
#pragma unroll
    for (int j = 0; j < 4; j++) {
        float d = vals[j] - mean;
        vs += d * d;
    }
#pragma unroll
    for (int off = 16; off >= 1; off >>= 1) vs += __shfl_xor_sync(0xffffffffu, vs, off);
    if (lane == 0) red[warp] = vs;
    __syncthreads();
    float tot2 = 0.f;
#pragma unroll
    for (int w = 0; w < 8; w++) tot2 += red[w];
    const float var = tot2 * (1.f / 1024.f);
    const float rstd = rsqrtf(var + 1e-8f);

#pragma unroll
    for (int j = 0; j < 4; j++) {
        int c = tid + j * 256;
        float v = (vals[j] - mean) * rstd * gam[c] + bet[c];
        xr[c] = v;
        g_xh[(size_t)row * DD + c] = hi16(v);
    }
}

// ---------------- host orchestration ----------------
extern "C" void kernel_launch(void* const* d_in, const int* in_sizes, int n_in,
                              void* d_out, int out_size) {
    const int*   ids   = (const int*)d_in[0];
    const int*   smask = (const int*)d_in[1];
    const int*   graph = (const int*)d_in[2];
    const float* emb   = (const float*)d_in[3];
    const float* w1    = (const float*)d_in[4];
    const float* b1    = (const float*)d_in[5];
    const float* w2    = (const float*)d_in[6];
    const float* b2    = (const float*)d_in[7];
    const float* pos   = (const float*)d_in[8];
    const float* wq    = (const float*)d_in[9];
    const float* bq    = (const float*)d_in[10];
    const float* wk    = (const float*)d_in[11];
    const float* bk    = (const float*)d_in[12];
    const float* wv    = (const float*)d_in[13];
    const float* bv    = (const float*)d_in[14];
    const float* ln1g  = (const float*)d_in[15];
    const float* ln1b  = (const float*)d_in[16];
    const float* fw1   = (const float*)d_in[17];
    const float* fb1   = (const float*)d_in[18];
    const float* fw2   = (const float*)d_in[19];
    const float* fb2   = (const float*)d_in[20];
    const float* ln2g  = (const float*)d_in[21];
    const float* ln2b  = (const float*)d_in[22];

    float *x, *o, *bqkvP;
    uint16_t *xeh, *xh, *h1h, *ffh, *qkvh, *qkvl, *ph, *pl;
    uint32_t *wh, *vth;
    cudaGetSymbolAddress((void**)&x,    g_x);
    cudaGetSymbolAddress((void**)&o,    g_o);
    cudaGetSymbolAddress((void**)&bqkvP,g_bqkv);
    cudaGetSymbolAddress((void**)&xeh,  g_xeh);
    cudaGetSymbolAddress((void**)&xh,   g_xh);
    cudaGetSymbolAddress((void**)&h1h,  g_h1h);
    cudaGetSymbolAddress((void**)&ffh,  g_ffh);
    cudaGetSymbolAddress((void**)&qkvh, g_qkvh);
    cudaGetSymbolAddress((void**)&qkvl, g_qkvl);
    cudaGetSymbolAddress((void**)&ph,   g_ph);
    cudaGetSymbolAddress((void**)&pl,   g_pl);
    cudaGetSymbolAddress((void**)&vth,  g_vth);
    cudaGetSymbolAddress((void**)&wh,   g_wh);

    const int SMW    = 3 * (128 * 80 + 128 * 80);            // 61440 (TERMS=1, 3-stage)
    const int SM256A = 2 * (2 * 256 * 80 + 64 * 80);         // 92160 (TERMS=2 AV)
    cudaFuncSetAttribute(hgemm<128,128,0,false,1>, cudaFuncAttributeMaxDynamicSharedMemorySize, SMW);
    cudaFuncSetAttribute(hgemm<128,128,1,true ,1>, cudaFuncAttributeMaxDynamicSharedMemorySize, SMW);
    cudaFuncSetAttribute(hgemm<128,128,3,true ,1>, cudaFuncAttributeMaxDynamicSharedMemorySize, SMW);
    cudaFuncSetAttribute(hgemm<256,64,2,false,2>,  cudaFuncAttributeMaxDynamicSharedMemorySize, SM256A);
    cudaFuncSetAttribute(attn_sm, cudaFuncAttributeMaxDynamicSharedMemorySize, SM_ATT);

    // launches 1-3 prep; launch #4 = weight hgemm (profiled)
    embed_gather<<<(NTOK * GDIM + 255) / 256, 256>>>(ids, emb);                                      // 1
    conv_xe<<<(NTOK * GPAD + 255) / 256, 256>>>();                                                   // 2
    pack_wt<<<dim3(MLPH / 32, GPAD / 64, 1), 256>>>(w1, wh + OFF_MLP1, GDIM, MLPH, GPAD, 0, 0);      // 3
    hgemm<128,128,3,true,1><<<dim3(MLPH / 128, NTOK / 128, 1), 128, SMW>>>(                          // 4 <- profiled
        xeh, nullptr, wh + OFF_MLP1, b1, nullptr, h1h, nullptr,
        NTOK, MLPH, GPAD, GPAD, GPAD / 2, MLPH, 0, 0, 0, 0, 0, 0);
    pack_wt<<<dim3(DD / 32, MLPH / 64, 1), 256>>>(w2, wh + OFF_MLP2, MLPH, DD, MLPH, 0, 0);
    hgemm<128,128,0,false,1><<<dim3(DD / 128, NTOK / 128, 1), 128, SMW>>>(
        h1h, nullptr, wh + OFF_MLP2, b2, x, nullptr, nullptr,
        NTOK, DD, MLPH, MLPH, MLPH / 2, DD, 0, 0, 0, 0, 0, 0);
    add_pos<<<(NTOK * DD) / 256, 256>>>(pos);

    // z-batched weight packs
    pack_wt<<<dim3(DD / 32, DD / 64, NBLK), 256>>>(wq, wh + OFF_QKV,               DD, DD, DD, (size_t)DD * DD, QKV_BLK);
    pack_wt<<<dim3(DD / 32, DD / 64, NBLK), 256>>>(wk, wh + OFF_QKV + QKV_MAT,     DD, DD, DD, (size_t)DD * DD, QKV_BLK);
    pack_wt<<<dim3(DD / 32, DD / 64, NBLK), 256>>>(wv, wh + OFF_QKV + 2 * QKV_MAT, DD, DD, DD, (size_t)DD * DD, QKV_BLK);
    pack_wt<<<dim3(FFH / 32, DD / 64, NBLK), 256>>>(fw1, wh + OFF_FF1, DD, FFH, DD, (size_t)DD * FFH, FF1_BLK);
    pack_wt<<<dim3(DD / 32, FFH / 64, NBLK), 256>>>(fw2, wh + OFF_FF2, FFH, DD, FFH, (size_t)FFH * DD, FF2_BLK);
    pack_bias<<<(NBLK * QKVW + 255) / 256, 256>>>(bq, bk, bv);

    for (int i = 0; i < NBLK; i++) {
        size_t oq = OFF_QKV + (size_t)i * QKV_BLK;
        hgemm<128,128,1,true,1><<<dim3(QKVW / 128, NTOK / 128, 1), 128, SMW>>>(
            xh, nullptr, wh + oq, bqkvP + i * QKVW, nullptr, qkvh, qkvl,
            NTOK, QKVW, DD, DD, DD / 2, QKVW, 0, 0, 0, 0, 0, 0);

        v_trans<<<dim3(4, BB * HH), 256>>>();

        // fused scores + masked softmax -> split-fp16 probs
        attn_sm<<<dim3(2, BB * HH), 256, SM_ATT>>>(qkvh, qkvl, smask, graph);

        // O = (Ph+Pl) @ Vh
        hgemm<256,64,2,false,2><<<dim3(1, 1, BB * HH), 128, SM256A>>>(
            ph, pl, vth, nullptr,
            o, nullptr, nullptr,
            TTOK, DH, TTOK, TTOK, TTOK / 2, DD,
            (size_t)HH * TTOK * TTOK, (size_t)TTOK * TTOK,
            (size_t)HH * DH * TTOK / 2, (size_t)DH * TTOK / 2,
            (size_t)TTOK * DD, DH);

        ln_res<<<NTOK, 256>>>(o, ln1g + i * DD, ln1b + i * DD);

        size_t o1 = OFF_FF1 + (size_t)i * FF1_BLK;
        size_t o2 = OFF_FF2 + (size_t)i * FF2_BLK;
        hgemm<128,128,3,true,1><<<dim3(FFH / 128, NTOK / 128, 1), 128, SMW>>>(
            xh, nullptr, wh + o1, fb1 + i * FFH, nullptr, ffh, nullptr,
            NTOK, FFH, DD, DD, DD / 2, FFH, 0, 0, 0, 0, 0, 0);
        hgemm<128,128,0,false,1><<<dim3(DD / 128, NTOK / 128, 1), 128, SMW>>>(
            ffh, nullptr, wh + o2, fb2 + i * DD, o, nullptr, nullptr,
            NTOK, DD, FFH, FFH, FFH / 2, DD, 0, 0, 0, 0, 0, 0);
        ln_res<<<NTOK, 256>>>(o, ln2g + i * DD, ln2b + i * DD);
    }

    cudaMemcpyAsync(d_out, x, sizeof(float) * NTOK * DD, cudaMemcpyDeviceToDevice);
}

// round 17
// speedup vs baseline: 1.0528x; 1.0528x over previous
#include <cuda_runtime.h>
#include <cuda_fp16.h>
#include <cstdint>

#define BB 16
#define TTOK 256
#define DD 1024
#define QKVW 3072
#define HH 16
#define NBLK 6
#define GDIM 300
#define GPAD 320
#define MLPH 2048
#define FFH 4096
#define DH 64
#define NTOK (BB*TTOK)   // 4096

// ---------------- scratch (device globals; no allocation allowed) ----------------
__device__ float g_xe [NTOK*GDIM];
__device__ float g_x  [NTOK*DD];
__device__ float g_o  [NTOK*DD];
__device__ float g_s  [(size_t)BB*HH*TTOK*TTOK];
__device__ float g_bqkv[NBLK*QKVW];
__device__ uint32_t g_mk[BB*TTOK*8];     // packed (key&graph) mask bits per (b,q)

// fp16 activations (hi planes; lo only where consumed)
__device__ __align__(16) uint16_t g_xeh[NTOK*GPAD];
__device__ __align__(16) uint16_t g_xh [NTOK*DD];
__device__ __align__(16) uint16_t g_h1h[NTOK*MLPH];
__device__ __align__(16) uint16_t g_ffh[(size_t)NTOK*FFH];
__device__ __align__(16) uint16_t g_qkvh[(size_t)NTOK*QKVW], g_qkvl[(size_t)NTOK*QKVW];
__device__ __align__(16) uint16_t g_ph[(size_t)BB*HH*TTOK*TTOK], g_pl[(size_t)BB*HH*TTOK*TTOK];
// V transposed per (b,h): [z][dh=64][keys/2=128 words] (hi only)
__device__ uint32_t g_vth[(size_t)BB*HH*DH*(TTOK/2)];

// packed fp16 weights (HI plane only), N-MAJOR: [N][K/2] fp16x2
#define OFF_MLP1 0ull
#define OFF_MLP2 327680ull
#define OFF_QKV  1376256ull
#define QKV_BLK  1572864ull
#define QKV_MAT  524288ull
#define OFF_FF1  10813440ull
#define FF1_BLK  2097152ull
#define OFF_FF2  23396352ull
#define FF2_BLK  2097152ull
#define W_TOTAL  35979264ull
__device__ uint32_t g_wh[W_TOTAL];

// ---------------- fp16 split helpers ----------------
__device__ __forceinline__ uint32_t pack_hi(float a, float b) {
    __half2 t = __floats2half2_rn(a, b);
    return *reinterpret_cast<uint32_t*>(&t);
}
__device__ __forceinline__ uint32_t pack_lo(float a, float b) {
    float ra = a - __half2float(__float2half_rn(a));
    float rb = b - __half2float(__float2half_rn(b));
    __half2 t = __floats2half2_rn(ra, rb);
    return *reinterpret_cast<uint32_t*>(&t);
}
__device__ __forceinline__ uint16_t hi16(float v) {
    __half h = __float2half_rn(v);
    return *reinterpret_cast<uint16_t*>(&h);
}
__device__ __forceinline__ uint16_t lo16(float v) {
    float r = v - __half2float(__float2half_rn(v));
    __half h = __float2half_rn(r);
    return *reinterpret_cast<uint16_t*>(&h);
}

// ---------------- transpose-pack: W[K][N] fp32 -> n-major [N][Kpad/2] fp16x2 (hi only) ----------------
__global__ void pack_wt(const float* __restrict__ W, uint32_t* __restrict__ oh,
                        int K, int N, int Kpad, size_t matStride, size_t outBlk) {
    __shared__ float st[64][33];
    W  += (size_t)blockIdx.z * matStride;
    oh += (size_t)blockIdx.z * outBlk;
    const int n0 = blockIdx.x * 32, k0 = blockIdx.y * 64;
    const int t = threadIdx.x;
    const int kk = t >> 5, n = t & 31;
#pragma unroll
    for (int i = 0; i < 8; i++) {
        int krow = k0 + kk + i * 8;
        st[kk + i * 8][n] = (krow < K) ? W[(size_t)krow * N + n0 + n] : 0.f;
    }
    __syncthreads();
    const int nn = t >> 3, c4 = (t & 7) * 4;
    uint32_t hv[4];
#pragma unroll
    for (int j = 0; j < 4; j++) {
        int k2 = c4 + j;
        hv[j] = pack_hi(st[2 * k2][nn], st[2 * k2 + 1][nn]);
    }
    size_t o = (size_t)(n0 + nn) * (Kpad >> 1) + (k0 >> 1) + c4;
    *(uint4*)(oh + o) = make_uint4(hv[0], hv[1], hv[2], hv[3]);
}

__global__ void pack_bias(const float* __restrict__ bq, const float* __restrict__ bk,
                          const float* __restrict__ bv) {
    int idx = blockIdx.x * 256 + threadIdx.x;
    if (idx >= NBLK * QKVW) return;
    int blk = idx / QKVW, n = idx - blk * QKVW;
    float v;
    if (n < DD)           v = bq[blk * DD + n];
    else if (n < 2 * DD)  v = bk[blk * DD + n - DD];
    else                  v = bv[blk * DD + n - 2 * DD];
    g_bqkv[idx] = v;
}

// ---------------- pack combined key/graph mask into bits ----------------
__global__ void pack_mask(const int* __restrict__ smask, const int* __restrict__ graph) {
    int idx = blockIdx.x * 256 + threadIdx.x;      // BB*TTOK*8 = 32768
    if (idx >= BB * TTOK * 8) return;
    int w = idx & 7, q = (idx >> 3) & (TTOK - 1), b = idx >> 11;
    const int* km = smask + b * TTOK;
    const int* gm = graph + ((size_t)b * TTOK + q) * TTOK;
    uint32_t bits = 0;
#pragma unroll
    for (int j = 0; j < 32; j++) {
        int c = w * 32 + j;
        if (km[c] > 0 && gm[c] > 0) bits |= 1u << j;
    }
    g_mk[idx] = bits;
}

// ---------------- embedding gather + hi-convert ----------------
__global__ void embed_gather(const int* __restrict__ ids, const float* __restrict__ emb) {
    int idx = blockIdx.x * blockDim.x + threadIdx.x;
    if (idx >= NTOK * GDIM) return;
    int bt = idx / GDIM;
    int c  = idx - bt * GDIM;
    g_xe[idx] = emb[(long long)ids[bt] * GDIM + c];
}
__global__ void conv_xe() {
    int idx = blockIdx.x * 256 + threadIdx.x;
    if (idx >= NTOK * GPAD) return;
    int m = idx / GPAD, k = idx - m * GPAD;
    float v = (k < GDIM) ? g_xe[m * GDIM + k] : 0.f;
    g_xeh[idx] = hi16(v);
}

__global__ void add_pos(const float* __restrict__ pos) {
    int idx = blockIdx.x * blockDim.x + threadIdx.x;
    if (idx >= NTOK * DD) return;
    float v = g_x[idx] + pos[idx % (TTOK * DD)];
    g_x[idx] = v;
    g_xh[idx] = hi16(v);
}

// ---------------- V transpose (hi plane only) ----------------
__global__ void __launch_bounds__(256) v_trans() {
    __shared__ uint16_t sh[64][65];
    const int kt = blockIdx.x, z = blockIdx.y;
    const int zb = z >> 4, zh = z & 15;
    const int t = threadIdx.x;
    const size_t base = (size_t)zb * TTOK * QKVW + 2 * DD + (size_t)zh * DH;
#pragma unroll
    for (int i = 0; i < 16; i++) {
        int e = t + i * 256;
        int r = e >> 6, c = e & 63;
        sh[r][c] = g_qkvh[base + (size_t)(kt * 64 + r) * QKVW + c];
    }
    __syncthreads();
    const int d = t >> 2, w0 = (t & 3) * 8;
    size_t ob = (size_t)z * (DH * TTOK / 2) + (size_t)d * (TTOK / 2) + kt * 32;
#pragma unroll
    for (int j = 0; j < 8; j++) {
        int w = w0 + j;
        g_vth[ob + w] = (uint32_t)sh[2 * w][d] | ((uint32_t)sh[2 * w + 1][d] << 16);
    }
}

// ---------------- async / mma helpers ----------------
__device__ __forceinline__ uint32_t smem_u32(const void* p) {
    uint32_t a;
    asm("{ .reg .u64 t; cvta.to.shared.u64 t, %1; cvt.u32.u64 %0, t; }" : "=r"(a) : "l"(p));
    return a;
}
__device__ __forceinline__ void cp16(uint32_t saddr, const void* g) {
    asm volatile("cp.async.cg.shared.global [%0], [%1], 16;" :: "r"(saddr), "l"(g));
}
__device__ __forceinline__ void cp_commit() {
    asm volatile("cp.async.commit_group;" ::: "memory");
}
template<int N>
__device__ __forceinline__ void cp_wait() {
    asm volatile("cp.async.wait_group %0;" :: "n"(N) : "memory");
}

#define MMA_F16(d, a, b)                                                         \
    asm volatile("mma.sync.aligned.m16n8k16.row.col.f32.f16.f16.f32 "            \
                 "{%0,%1,%2,%3},{%4,%5,%6,%7},{%8,%9},{%0,%1,%2,%3};"            \
                 : "+f"(d[0]), "+f"(d[1]), "+f"(d[2]), "+f"(d[3])                 \
                 : "r"(a[0]), "r"(a[1]), "r"(a[2]), "r"(a[3]), "r"(b[0]), "r"(b[1]))

#define LDSM4(r0, r1, r2, r3, addr)                                              \
    asm volatile("ldmatrix.sync.aligned.m8n8.x4.shared.b16 {%0,%1,%2,%3}, [%4];" \
                 : "=r"(r0), "=r"(r1), "=r"(r2), "=r"(r3) : "r"(addr))

// ---------------- generalized fp16 HGEMM ----------------
// C[z] = [relu](A[z] @ W[z]^T(n-major) + bias). ktile=32 (80B rows), 4 warps.
// TERMS=1: Ah@Wh, 3-stage, ONE barrier/ktile. TERMS=2: (Ah+Al)@Wh, 2-stage (attention).
// MODE 0: fp32 +bias. MODE 1: split fp16 hi+lo(+bias, lo only for cols<loN).
// MODE 2: fp32 no bias. MODE 3: fp16 hi +bias.
template<int MT, int NT, int MODE, bool RELU, int TERMS>
__global__ void __launch_bounds__(128, 2)
hgemm(const uint16_t* __restrict__ Ah, const uint16_t* __restrict__ Al,
      const uint32_t* __restrict__ Wh,
      const float* __restrict__ bias,
      float* __restrict__ C, uint16_t* __restrict__ Ch, uint16_t* __restrict__ Cl, int loN,
      int M, int N, int K, int sA, int sWw, int sC,
      size_t ozAb, size_t ozAh, size_t ozWb, size_t ozWh, size_t ozCb, size_t ozCh) {
    constexpr int APL  = MT * 80;
    constexpr int WPL  = NT * 80;
    constexpr int APLN = (TERMS >= 2) ? 2 : 1;
    constexpr int ALO  = APL;
    constexpr int WOFF = APLN * APL;
    constexpr int STG  = APLN * APL + WPL;
    constexpr int NSTG = (TERMS >= 2) ? 2 : 3;

    extern __shared__ char smc[];
    const uint32_t smb = smem_u32(smc);
    const int tid  = threadIdx.x;
    const int lane = tid & 31, warp = tid >> 5;
    const int wm   = (MT == 256) ? warp * 64 : (warp >> 1) * 64;
    const int wn   = (MT == 256) ? 0         : (warp & 1) * 64;
    const int group = lane >> 2, quad = lane & 3;
    const int row0 = blockIdx.y * MT;
    const int col0 = blockIdx.x * NT;

    const int z = blockIdx.z, zb = z >> 4, zh = z & 15;
    Ah += zb * ozAb + zh * ozAh;
    if (TERMS >= 2) Al += zb * ozAb + zh * ozAh;
    Wh += zb * ozWb + zh * ozWh;
    const size_t czoff = zb * ozCb + zh * ozCh;

    const int sub = lane >> 3, rr = lane & 7;
    const uint32_t aOff = ((wm + (sub & 1) * 8 + rr) * 40 + (sub >> 1) * 8) * 2;
    const uint32_t wOff = WOFF + ((wn + (sub >> 1) * 8 + rr) * 20 + (sub & 1) * 4) * 4;

    float acc[4][8][4];
#pragma unroll
    for (int i = 0; i < 4; i++)
#pragma unroll
        for (int j = 0; j < 8; j++)
#pragma unroll
            for (int e = 0; e < 4; e++) acc[i][j][e] = 0.f;

    const int iters = K >> 5;

    auto fill = [&](int stage, int k0) {
        uint32_t sb = smb + stage * STG;
#pragma unroll
        for (int i = 0; i < MT / 32; i++) {
            int c = tid + i * 128;
            int row = c >> 2, kc = c & 3;
            size_t g = (size_t)(row0 + row) * sA + k0 + kc * 8;
            uint32_t so = sb + row * 80 + kc * 16;
            cp16(so, Ah + g);
            if (TERMS >= 2) cp16(so + ALO, Al + g);
        }
        const int k2b = k0 >> 1;
#pragma unroll
        for (int i = 0; i < NT / 32; i++) {
            int c = tid + i * 128;
            int row = c >> 2, ch = c & 3;
            size_t g = (size_t)(col0 + row) * sWw + k2b + ch * 4;
            uint32_t so = sb + WOFF + row * 80 + ch * 16;
            cp16(so, Wh + g);
        }
    };

    auto compute = [&](int stage) {
        const uint32_t aBase = smb + stage * STG + aOff;
        const uint32_t wBase = smb + stage * STG + wOff;
#pragma unroll
        for (int ks = 0; ks < 2; ks++) {
            uint32_t wh_[4][4];
#pragma unroll
            for (int p = 0; p < 4; p++) {
                LDSM4(wh_[p][0], wh_[p][1], wh_[p][2], wh_[p][3], wBase + p * 1280 + ks * 32);
            }
#pragma unroll
            for (int mt = 0; mt < 4; mt++) {
                uint32_t ah[4], al[4];
                LDSM4(ah[0], ah[1], ah[2], ah[3], aBase + mt * 1280 + ks * 32);
                if (TERMS >= 2)
                    LDSM4(al[0], al[1], al[2], al[3], aBase + ALO + mt * 1280 + ks * 32);
#pragma unroll
                for (int nt = 0; nt < 8; nt++) MMA_F16(acc[mt][nt], ah, (&wh_[nt >> 1][(nt & 1) * 2]));
                if (TERMS >= 2) {
#pragma unroll
                    for (int nt = 0; nt < 8; nt++) MMA_F16(acc[mt][nt], al, (&wh_[nt >> 1][(nt & 1) * 2]));
                }
            }
        }
    };

    if (TERMS == 1) {
        fill(0, 0); cp_commit();
        if (iters > 1) { fill(1, 32); cp_commit(); }
        for (int it = 0; it < iters; ++it) {
            if (it + 1 < iters) cp_wait<1>(); else cp_wait<0>();
            __syncthreads();
            if (it + 2 < iters) { fill((it + 2) % NSTG, (it + 2) * 32); cp_commit(); }
            compute(it % NSTG);
        }
        __syncthreads();
    } else {
        fill(0, 0); cp_commit();
        for (int it = 0; it < iters; ++it) {
            if (it + 1 < iters) { fill((it + 1) & 1, (it + 1) * 32); cp_commit(); cp_wait<1>(); }
            else cp_wait<0>();
            __syncthreads();
            compute(it & 1);
            __syncthreads();
        }
    }

    // ---- epilogue ----
#pragma unroll
    for (int mt = 0; mt < 4; mt++) {
        int r = row0 + wm + mt * 16 + group;
#pragma unroll
        for (int nt = 0; nt < 8; nt++) {
            int c  = col0 + wn + nt * 8 + quad * 2;
            float b0 = 0.f, b1 = 0.f;
            if (MODE != 2) { b0 = bias[c]; b1 = bias[c + 1]; }
            float v0 = acc[mt][nt][0] + b0;
            float v1 = acc[mt][nt][1] + b1;
            float v2 = acc[mt][nt][2] + b0;
            float v3 = acc[mt][nt][3] + b1;
            if (RELU) {
                v0 = fmaxf(v0, 0.f); v1 = fmaxf(v1, 0.f);
                v2 = fmaxf(v2, 0.f); v3 = fmaxf(v3, 0.f);
            }
            if (MODE == 1 || MODE == 3) {
                uint32_t* ChW = (uint32_t*)Ch;
                size_t i0 = (czoff + (size_t)r * sC + c) >> 1;
                size_t i1 = (czoff + (size_t)(r + 8) * sC + c) >> 1;
                ChW[i0] = pack_hi(v0, v1);
                ChW[i1] = pack_hi(v2, v3);
                if (MODE == 1 && c < loN) {
                    uint32_t* ClW = (uint32_t*)Cl;
                    ClW[i0] = pack_lo(v0, v1);
                    ClW[i1] = pack_lo(v2, v3);
                }
            } else {
                *(float2*)&C[czoff + (size_t)r * sC + c]       = make_float2(v0, v1);
                *(float2*)&C[czoff + (size_t)(r + 8) * sC + c] = make_float2(v2, v3);
            }
        }
    }
}

// ---------------- masked softmax (bit-packed mask): fp32 scores -> split-fp16 probs ----------------
__global__ void __launch_bounds__(256) softmax_kernel(const int* __restrict__ smask) {
    const int warp = threadIdx.x >> 5, lane = threadIdx.x & 31;
    const int r = blockIdx.x * 8 + warp;
    const int b = r >> 12;
    const int q = r & (TTOK - 1);
    const float* row = g_s + (size_t)r * TTOK;
    const uint32_t* mk = g_mk + ((size_t)(b * TTOK + q)) * 8;
    const float NEGF = -4294967295.0f;

    float v[8];
    float m = -3.4e38f;
#pragma unroll
    for (int j = 0; j < 8; j++) {
        int c = lane + j * 32;
        float s = row[c] * 0.125f;
        if (!((mk[j] >> lane) & 1u)) s = NEGF;
        v[j] = s;
        m = fmaxf(m, s);
    }
#pragma unroll
    for (int off = 16; off >= 1; off >>= 1)
        m = fmaxf(m, __shfl_xor_sync(0xffffffffu, m, off));
    float sum = 0.f;
#pragma unroll
    for (int j = 0; j < 8; j++) {
        v[j] = expf(v[j] - m);
        sum += v[j];
    }
#pragma unroll
    for (int off = 16; off >= 1; off >>= 1)
        sum += __shfl_xor_sync(0xffffffffu, sum, off);
    float qs = (float)smask[b * TTOK + q];
    float inv = qs / sum;
#pragma unroll
    for (int j = 0; j < 8; j++) {
        int c = lane + j * 32;
        float p = v[j] * inv;
        g_ph[(size_t)r * TTOK + c] = hi16(p);
        g_pl[(size_t)r * TTOK + c] = lo16(p);
    }
}

// ---------------- residual + layernorm (+ hi write) ----------------
__global__ void __launch_bounds__(256) ln_res(const float* __restrict__ addsrc,
                                              const float* __restrict__ gam,
                                              const float* __restrict__ bet) {
    const int row = blockIdx.x;
    const int tid = threadIdx.x;
    const int warp = tid >> 5, lane = tid & 31;
    float* xr = g_x + (size_t)row * DD;
    const float* ar = addsrc + (size_t)row * DD;
    __shared__ float red[8];

    float vals[4];
    float s = 0.f;
#pragma unroll
    for (int j = 0; j < 4; j++) {
        int c = tid + j * 256;
        vals[j] = xr[c] + ar[c];
        s += vals[j];
    }
#pragma unroll
    for (int off = 16; off >= 1; off >>= 1) s += __shfl_xor_sync(0xffffffffu, s, off);
    if (lane == 0) red[warp] = s;
    __syncthreads();
    float tot = 0.f;
#pragma unroll
    for (int w = 0; w < 8; w++) tot += red[w];
    const float mean = tot * (1.f / 1024.f);
    __syncthreads();

    float vs = 0.f;
#pragma unroll
    for (int j = 0; j < 4; j++) {
        float d = vals[j] - mean;
        vs += d * d;
    }
#pragma unroll
    for (int off = 16; off >= 1; off >>= 1) vs += __shfl_xor_sync(0xffffffffu, vs, off);
    if (lane == 0) red[warp] = vs;
    __syncthreads();
    float tot2 = 0.f;
#pragma unroll
    for (int w = 0; w < 8; w++) tot2 += red[w];
    const float var = tot2 * (1.f / 1024.f);
    const float rstd = rsqrtf(var + 1e-8f);

#pragma unroll
    for (int j = 0; j < 4; j++) {
        int c = tid + j * 256;
        float v = (vals[j] - mean) * rstd * gam[c] + bet[c];
        xr[c] = v;
        g_xh[(size_t)row * DD + c] = hi16(v);
    }
}

// ---------------- host orchestration ----------------
extern "C" void kernel_launch(void* const* d_in, const int* in_sizes, int n_in,
                              void* d_out, int out_size) {
    const int*   ids   = (const int*)d_in[0];
    const int*   smask = (const int*)d_in[1];
    const int*   graph = (const int*)d_in[2];
    const float* emb   = (const float*)d_in[3];
    const float* w1    = (const float*)d_in[4];
    const float* b1    = (const float*)d_in[5];
    const float* w2    = (const float*)d_in[6];
    const float* b2    = (const float*)d_in[7];
    const float* pos   = (const float*)d_in[8];
    const float* wq    = (const float*)d_in[9];
    const float* bq    = (const float*)d_in[10];
    const float* wk    = (const float*)d_in[11];
    const float* bk    = (const float*)d_in[12];
    const float* wv    = (const float*)d_in[13];
    const float* bv    = (const float*)d_in[14];
    const float* ln1g  = (const float*)d_in[15];
    const float* ln1b  = (const float*)d_in[16];
    const float* fw1   = (const float*)d_in[17];
    const float* fb1   = (const float*)d_in[18];
    const float* fw2   = (const float*)d_in[19];
    const float* fb2   = (const float*)d_in[20];
    const float* ln2g  = (const float*)d_in[21];
    const float* ln2b  = (const float*)d_in[22];

    float *x, *o, *s, *bqkvP;
    uint16_t *xeh, *xh, *h1h, *ffh, *qkvh, *qkvl, *ph, *pl;
    uint32_t *wh, *vth;
    cudaGetSymbolAddress((void**)&x,    g_x);
    cudaGetSymbolAddress((void**)&o,    g_o);
    cudaGetSymbolAddress((void**)&s,    g_s);
    cudaGetSymbolAddress((void**)&bqkvP,g_bqkv);
    cudaGetSymbolAddress((void**)&xeh,  g_xeh);
    cudaGetSymbolAddress((void**)&xh,   g_xh);
    cudaGetSymbolAddress((void**)&h1h,  g_h1h);
    cudaGetSymbolAddress((void**)&ffh,  g_ffh);
    cudaGetSymbolAddress((void**)&qkvh, g_qkvh);
    cudaGetSymbolAddress((void**)&qkvl, g_qkvl);
    cudaGetSymbolAddress((void**)&ph,   g_ph);
    cudaGetSymbolAddress((void**)&pl,   g_pl);
    cudaGetSymbolAddress((void**)&vth,  g_vth);
    cudaGetSymbolAddress((void**)&wh,   g_wh);

    const int SMW    = 3 * (128 * 80 + 128 * 80);            // 61440 (TERMS=1, 3-stage)
    const int SM128A = 2 * (2 * 128 * 80 + 128 * 80);        // 61440 (TERMS=2 scores)
    const int SM256A = 2 * (2 * 256 * 80 + 64 * 80);         // 92160 (TERMS=2 AV)
    cudaFuncSetAttribute(hgemm<128,128,0,false,1>, cudaFuncAttributeMaxDynamicSharedMemorySize, SMW);
    cudaFuncSetAttribute(hgemm<128,128,1,true ,1>, cudaFuncAttributeMaxDynamicSharedMemorySize, SMW);
    cudaFuncSetAttribute(hgemm<128,128,3,true ,1>, cudaFuncAttributeMaxDynamicSharedMemorySize, SMW);
    cudaFuncSetAttribute(hgemm<128,128,2,false,2>, cudaFuncAttributeMaxDynamicSharedMemorySize, SM128A);
    cudaFuncSetAttribute(hgemm<256,64,2,false,2>,  cudaFuncAttributeMaxDynamicSharedMemorySize, SM256A);

    // launches 1-3 prep; launch #4 = weight hgemm (profiled)
    embed_gather<<<(NTOK * GDIM + 255) / 256, 256>>>(ids, emb);                                      // 1
    conv_xe<<<(NTOK * GPAD + 255) / 256, 256>>>();                                                   // 2
    pack_wt<<<dim3(MLPH / 32, GPAD / 64, 1), 256>>>(w1, wh + OFF_MLP1, GDIM, MLPH, GPAD, 0, 0);      // 3
    hgemm<128,128,3,true,1><<<dim3(MLPH / 128, NTOK / 128, 1), 128, SMW>>>(                          // 4 <- profiled
        xeh, nullptr, wh + OFF_MLP1, b1, nullptr, h1h, nullptr, 0,
        NTOK, MLPH, GPAD, GPAD, GPAD / 2, MLPH, 0, 0, 0, 0, 0, 0);
    pack_wt<<<dim3(DD / 32, MLPH / 64, 1), 256>>>(w2, wh + OFF_MLP2, MLPH, DD, MLPH, 0, 0);
    hgemm<128,128,0,false,1><<<dim3(DD / 128, NTOK / 128, 1), 128, SMW>>>(
        h1h, nullptr, wh + OFF_MLP2, b2, x, nullptr, nullptr, 0,
        NTOK, DD, MLPH, MLPH, MLPH / 2, DD, 0, 0, 0, 0, 0, 0);
    add_pos<<<(NTOK * DD) / 256, 256>>>(pos);

    // z-batched weight packs + mask pack
    pack_wt<<<dim3(DD / 32, DD / 64, NBLK), 256>>>(wq, wh + OFF_QKV,               DD, DD, DD, (size_t)DD * DD, QKV_BLK);
    pack_wt<<<dim3(DD / 32, DD / 64, NBLK), 256>>>(wk, wh + OFF_QKV + QKV_MAT,     DD, DD, DD, (size_t)DD * DD, QKV_BLK);
    pack_wt<<<dim3(DD / 32, DD / 64, NBLK), 256>>>(wv, wh + OFF_QKV + 2 * QKV_MAT, DD, DD, DD, (size_t)DD * DD, QKV_BLK);
    pack_wt<<<dim3(FFH / 32, DD / 64, NBLK), 256>>>(fw1, wh + OFF_FF1, DD, FFH, DD, (size_t)DD * FFH, FF1_BLK);
    pack_wt<<<dim3(DD / 32, FFH / 64, NBLK), 256>>>(fw2, wh + OFF_FF2, FFH, DD, FFH, (size_t)FFH * DD, FF2_BLK);
    pack_bias<<<(NBLK * QKVW + 255) / 256, 256>>>(bq, bk, bv);
    pack_mask<<<(BB * TTOK * 8 + 255) / 256, 256>>>(smask, graph);

    for (int i = 0; i < NBLK; i++) {
        size_t oq = OFF_QKV + (size_t)i * QKV_BLK;
        // fused QKV (1-term) -> fp16 hi everywhere, lo only for Q cols (< DD)
        hgemm<128,128,1,true,1><<<dim3(QKVW / 128, NTOK / 128, 1), 128, SMW>>>(
            xh, nullptr, wh + oq, bqkvP + i * QKVW, nullptr, qkvh, qkvl, DD,
            NTOK, QKVW, DD, DD, DD / 2, QKVW, 0, 0, 0, 0, 0, 0);

        v_trans<<<dim3(4, BB * HH), 256>>>();

        // scores: 2-term (Qh+Ql)@Kh
        hgemm<128,128,2,false,2><<<dim3(2, 2, BB * HH), 128, SM128A>>>(
            qkvh, qkvl, (uint32_t*)qkvh + DD / 2,
            nullptr, s, nullptr, nullptr, 0,
            TTOK, TTOK, DH, QKVW, QKVW / 2, TTOK,
            (size_t)TTOK * QKVW, DH, (size_t)TTOK * QKVW / 2, DH / 2,
            (size_t)HH * TTOK * TTOK, (size_t)TTOK * TTOK);

        softmax_kernel<<<(BB * HH * TTOK) / 8, 256>>>(smask);

        // O = (Ph+Pl) @ Vh
        hgemm<256,64,2,false,2><<<dim3(1, 1, BB * HH), 128, SM256A>>>(
            ph, pl, vth,
            nullptr, o, nullptr, nullptr, 0,
            TTOK, DH, TTOK, TTOK, TTOK / 2, DD,
            (size_t)HH * TTOK * TTOK, (size_t)TTOK * TTOK,
            (size_t)HH * DH * TTOK / 2, (size_t)DH * TTOK / 2,
            (size_t)TTOK * DD, DH);

        ln_res<<<NTOK, 256>>>(o, ln1g + i * DD, ln1b + i * DD);

        size_t o1 = OFF_FF1 + (size_t)i * FF1_BLK;
        size_t o2 = OFF_FF2 + (size_t)i * FF2_BLK;
        hgemm<128,128,3,true,1><<<dim3(FFH / 128, NTOK / 128, 1), 128, SMW>>>(
            xh, nullptr, wh + o1, fb1 + i * FFH, nullptr, ffh, nullptr, 0,
            NTOK, FFH, DD, DD, DD / 2, FFH, 0, 0, 0, 0, 0, 0);
        hgemm<128,128,0,false,1><<<dim3(DD / 128, NTOK / 128, 1), 128, SMW>>>(
            ffh, nullptr, wh + o2, fb2 + i * DD, o, nullptr, nullptr, 0,
            NTOK, DD, FFH, FFH, FFH / 2, DD, 0, 0, 0, 0, 0, 0);
        ln_res<<<NTOK, 256>>>(o, ln2g + i * DD, ln2b + i * DD);
    }

    cudaMemcpyAsync(d_out, x, sizeof(float) * NTOK * DD, cudaMemcpyDeviceToDevice);
}